// round 6
// baseline (speedup 1.0000x reference)
#include <cuda_runtime.h>
#include <math.h>

// Problem constants
#define H    2048
#define E    8
#define I16  16
#define NTOK 8192
#define NB   64            // bucket ids lo*8+hi (28 valid)
#define TB   64            // tokens per tile
#define KC   128           // k-chunk (phase A)
#define NCH  (H / KC)      // 16
#define XP   132           // X/D row pitch (floats), mod 32 = 4
#define ASP  68            // Red pitch over tokens
#define AIP  36            // As pitch over i (As[t][i])

// smem layout (float offsets)
#define XDSZ     (96 * XP)                 // one X+D buffer: 12672 floats
#define RED_OFF  (2 * XDSZ)                // 25344
#define AS_OFF   (RED_OFF + 8 * 32 * ASP)  // 42752
#define SM_FLOATS (AS_OFF + TB * AIP)      // 45056 floats = 180224 B

// f32x2 packed-math helpers
#define FMA2(d, a, b) asm("fma.rn.f32x2 %0, %1, %2, %0;" : "+l"(d) : "l"(a), "l"(b))
#define UNPACK2(lo, hi, d) asm("mov.b64 {%0, %1}, %2;" : "=f"(lo), "=f"(hi) : "l"(d))

__device__ __forceinline__ unsigned su32(const void* p) {
    return (unsigned)__cvta_generic_to_shared(p);
}
#define CP16(dst, src) asm volatile("cp.async.cg.shared.global [%0], [%1], 16;" :: "r"(dst), "l"(src))
#define CP_COMMIT()    asm volatile("cp.async.commit_group;" ::: "memory")
#define CP_WAIT1()     asm volatile("cp.async.wait_group 1;" ::: "memory")
#define CP_WAIT0()     asm volatile("cp.async.wait_group 0;" ::: "memory")

// ---------------- device scratch ----------------
__device__ int    g_count[NB];
__device__ int    g_tok[NB][NTOK];
__device__ float2 g_gate[NB][NTOK];

// ---------------- K1: router (8 tokens per warp, f32x2) ----------------
__global__ __launch_bounds__(256)
void router_kernel(const float* __restrict__ x,
                   const float* __restrict__ rw) {
    extern __shared__ float Rs[];   // [E][H] = 64 KB
    for (int idx = threadIdx.x; idx < (E * H) / 4; idx += blockDim.x)
        ((float4*)Rs)[idx] = ((const float4*)rw)[idx];
    __syncthreads();

    const int w = threadIdx.x >> 5;
    const int l = threadIdx.x & 31;
    const int t0 = blockIdx.x * 64 + w * 8;

    const ulonglong2* xr = (const ulonglong2*)(x + (size_t)t0 * H);

    unsigned long long acc[E][8];
#pragma unroll
    for (int e = 0; e < E; e++)
#pragma unroll
        for (int j = 0; j < 8; j++) acc[e][j] = 0ull;

    for (int s = 0; s < 16; s++) {
        ulonglong2 xv[8];
#pragma unroll
        for (int j = 0; j < 8; j++)
            xv[j] = xr[j * (H / 4) + l + 32 * s];
#pragma unroll
        for (int e = 0; e < E; e++) {
            ulonglong2 wv = ((const ulonglong2*)(Rs + e * H))[l + 32 * s];
#pragma unroll
            for (int j = 0; j < 8; j++) {
                FMA2(acc[e][j], xv[j].x, wv.x);
                FMA2(acc[e][j], xv[j].y, wv.y);
            }
        }
    }

    float lg[E];
#pragma unroll
    for (int e = 0; e < E; e++) {
#pragma unroll
        for (int j = 0; j < 8; j++) {
            float s0, s1;
            UNPACK2(s0, s1, acc[e][j]);
            float v = s0 + s1;
#pragma unroll
            for (int o = 16; o > 0; o >>= 1) v += __shfl_xor_sync(0xffffffffu, v, o);
            if (l == j) lg[e] = v;
        }
    }

    if (l < 8) {
        int t = t0 + l;
        float m = lg[0];
#pragma unroll
        for (int e = 1; e < E; e++) m = fmaxf(m, lg[e]);
        float wgt[E]; float ssum = 0.f;
#pragma unroll
        for (int e = 0; e < E; e++) { wgt[e] = __expf(lg[e] - m); ssum += wgt[e]; }
        float inv = 1.f / ssum;

        int i1 = 0; float v1 = wgt[0];
#pragma unroll
        for (int e = 1; e < E; e++) if (wgt[e] > v1) { v1 = wgt[e]; i1 = e; }
        int i2 = -1; float v2 = -1.f;
#pragma unroll
        for (int e = 0; e < E; e++)
            if (e != i1 && wgt[e] > v2) { v2 = wgt[e]; i2 = e; }

        float g1 = v1 * inv, g2 = v2 * inv;
        int lo, hi; float glo, ghi;
        if (i1 < i2) { lo = i1; hi = i2; glo = g1; ghi = g2; }
        else         { lo = i2; hi = i1; glo = g2; ghi = g1; }
        int p = lo * 8 + hi;
        int slot = atomicAdd(&g_count[p], 1);
        g_tok[p][slot]  = t;
        g_gate[p][slot] = make_float2(glo, ghi);
    }
}

// ---------------- K2: expert compute, flat tile queue ----------------
__global__ __launch_bounds__(256, 1)
void expert_kernel(const float* __restrict__ x,
                   const float* __restrict__ dw,
                   const float* __restrict__ uw,
                   float* __restrict__ out) {
    extern __shared__ float sm[];
    float* Red = sm + RED_OFF;
    float* As  = sm + AS_OFF;

    __shared__ int    pref[NB + 1];
    __shared__ int    Ts[TB];
    __shared__ float2 Gs[TB];

    const int tid = threadIdx.x;
    const int w = tid >> 5;
    const int l = tid & 31;
    // phase A lane ids
    const int tg = l & 7;
    const int ig = l >> 3;

    // build flat tile prefix over buckets
    if (tid < NB) {
        int lo_ = tid >> 3, hi_ = tid & 7;
        pref[tid + 1] = (lo_ < hi_) ? (g_count[tid] + TB - 1) / TB : 0;
    }
    __syncthreads();
    if (tid == 0) {
        int s = 0;
        pref[0] = 0;
        for (int i = 1; i <= NB; i++) { s += pref[i]; pref[i] = s; }
    }
    __syncthreads();
    const int ntiles = pref[NB];

    for (int ft = blockIdx.x; ft < ntiles; ft += gridDim.x) {
        // binary search: largest p with pref[p] <= ft
        int a = 0, b = NB;
        while (b - a > 1) { int mM = (a + b) >> 1; if (pref[mM] <= ft) a = mM; else b = mM; }
        const int p  = a;
        const int lo = p >> 3, hi = p & 7;
        const int cnt  = g_count[p];
        const int base = (ft - pref[p]) * TB;
        const int n    = min(TB, cnt - base);

        __syncthreads();             // prev tile done reading Ts/Gs/As
        if (tid < TB) {
            int src = base + ((tid < n) ? tid : 0);
            Ts[tid] = g_tok[p][src];
            float2 gg = g_gate[p][src];
            if (tid >= n) gg = make_float2(0.f, 0.f);
            Gs[tid] = gg;
        }
        __syncthreads();

        // ================= Phase A =================
        unsigned long long accP[8][8];
#pragma unroll
        for (int u = 0; u < 8; u++)
#pragma unroll
            for (int v = 0; v < 8; v++) accP[u][v] = 0ull;

        auto stage = [&](int c, int bb) {
            float* dst = sm + bb * XDSZ;
            int koff = c * KC;
#pragma unroll
            for (int j = 0; j < 8; j++) {
                int idx = tid + 256 * j, r = idx >> 5, q = idx & 31;
                CP16(su32(dst + r * XP + 4 * q),
                     x + (size_t)Ts[r] * H + koff + 4 * q);
            }
#pragma unroll
            for (int j = 0; j < 4; j++) {
                int idx = tid + 256 * j, r = idx >> 5, q = idx & 31;
                int e = (r < 16) ? lo : hi;
                CP16(su32(dst + (64 + r) * XP + 4 * q),
                     dw + (size_t)(e * I16 + (r & 15)) * H + koff + 4 * q);
            }
        };

        stage(0, 0); CP_COMMIT();
        stage(1, 1); CP_COMMIT();

        for (int c = 0; c < NCH; c++) {
            if (c == NCH - 1) { CP_WAIT0(); } else { CP_WAIT1(); }
            __syncthreads();
            const ulonglong2* B4 = (const ulonglong2*)(sm + (c & 1) * XDSZ);

#pragma unroll
            for (int q2 = 0; q2 < 4; q2++) {
                const int kq = (w << 2) + q2;
                ulonglong2 xv[8];
#pragma unroll
                for (int u = 0; u < 8; u++)
                    xv[u] = B4[(tg + 8 * u) * 33 + kq];
#pragma unroll
                for (int v = 0; v < 8; v++) {
                    ulonglong2 dv = B4[(64 + ig + 4 * v) * 33 + kq];
#pragma unroll
                    for (int u = 0; u < 8; u++) {
                        FMA2(accP[u][v], xv[u].x, dv.x);
                        FMA2(accP[u][v], xv[u].y, dv.y);
                    }
                }
            }
            __syncthreads();
            if (c + 2 < NCH) { stage(c + 2, c & 1); CP_COMMIT(); }
        }

        // split-K partials -> Red[w][i][t]
#pragma unroll
        for (int u = 0; u < 8; u++)
#pragma unroll
            for (int v = 0; v < 8; v++) {
                float s0, s1;
                UNPACK2(s0, s1, accP[u][v]);
                Red[w * (32 * ASP) + (ig + 4 * v) * ASP + (tg + 8 * u)] = s0 + s1;
            }
        __syncthreads();

        // reduce + silu + gate -> As[t][i]
#pragma unroll
        for (int j = 0; j < 8; j++) {
            int idx = j * 256 + tid;
            int i = idx >> 6, t = idx & 63;
            float hv = 0.f;
#pragma unroll
            for (int kk = 0; kk < 8; kk++)
                hv += Red[kk * (32 * ASP) + i * ASP + t];
            float2 gg = Gs[t];
            float gate = (i < 16) ? gg.x : gg.y;
            float sig = 1.f / (1.f + __expf(-hv));
            As[t * AIP + i] = gate * hv * sig;
        }
        __syncthreads();

        // ================= Phase B =================
        // warp w -> tokens w*8..w*8+7; lane l -> 4 contiguous h per pass.
        // f32x2 packed over i-pairs; U read via LDG (L1/L2 resident).
        const float* ulo = uw + ((size_t)lo * H) * I16;
        const float* uhi = uw + ((size_t)hi * H) * I16;
        const float* Ab  = As + (w * 8) * AIP;

        for (int pass = 0; pass < 16; pass++) {
            const int hb = pass * 128 + 4 * l;
            unsigned long long acc2[8][4];
#pragma unroll
            for (int j = 0; j < 8; j++)
#pragma unroll
                for (int hh = 0; hh < 4; hh++) acc2[j][hh] = 0ull;

#pragma unroll
            for (int kq = 0; kq < 8; kq++) {
                const float* ub = ((kq < 4) ? ulo : uhi) + (size_t)hb * I16 + 4 * (kq & 3);
                ulonglong2 uv[4];
#pragma unroll
                for (int hh = 0; hh < 4; hh++)
                    uv[hh] = *(const ulonglong2*)(ub + hh * I16);
#pragma unroll
                for (int j = 0; j < 8; j++) {
                    ulonglong2 av = *(const ulonglong2*)(Ab + j * AIP + 4 * kq);
#pragma unroll
                    for (int hh = 0; hh < 4; hh++) {
                        FMA2(acc2[j][hh], av.x, uv[hh].x);
                        FMA2(acc2[j][hh], av.y, uv[hh].y);
                    }
                }
            }

#pragma unroll
            for (int j = 0; j < 8; j++) {
                int tl = w * 8 + j;
                if (tl < n) {
                    float4 ov;
                    float s0, s1;
                    UNPACK2(s0, s1, acc2[j][0]); ov.x = s0 + s1;
                    UNPACK2(s0, s1, acc2[j][1]); ov.y = s0 + s1;
                    UNPACK2(s0, s1, acc2[j][2]); ov.z = s0 + s1;
                    UNPACK2(s0, s1, acc2[j][3]); ov.w = s0 + s1;
                    *(float4*)(out + (size_t)Ts[tl] * H + hb) = ov;
                }
            }
        }
    }
}

// ---------------- launch ----------------
extern "C" void kernel_launch(void* const* d_in, const int* in_sizes, int n_in,
                              void* d_out, int out_size) {
    const float* x  = (const float*)d_in[0];
    const float* rw = (const float*)d_in[1];
    const float* dw = (const float*)d_in[2];
    const float* uw = (const float*)d_in[3];
    float* out = (float*)d_out;

    const int rs_smem = E * H * sizeof(float);     // 64 KB
    const int ek_smem = SM_FLOATS * sizeof(float); // 180224 B
    cudaFuncSetAttribute(router_kernel, cudaFuncAttributeMaxDynamicSharedMemorySize, rs_smem);
    cudaFuncSetAttribute(expert_kernel, cudaFuncAttributeMaxDynamicSharedMemorySize, ek_smem);

    void* cnt_ptr = nullptr;
    cudaGetSymbolAddress(&cnt_ptr, g_count);
    cudaMemsetAsync(cnt_ptr, 0, NB * sizeof(int));

    router_kernel<<<NTOK / 64, 256, rs_smem>>>(x, rw);
    expert_kernel<<<148, 256, ek_smem>>>(x, dw, uw, out);
}

// round 7
// speedup vs baseline: 1.6201x; 1.6201x over previous
#include <cuda_runtime.h>
#include <math.h>

// Problem constants
#define H    2048
#define E    8
#define I16  16
#define NTOK 8192
#define NB   64            // bucket ids lo*8+hi (28 valid)
#define TB   64            // tokens per tile
#define KC   128           // k-chunk (phase A)
#define NCH  (H / KC)      // 16
#define XP   132           // X/D row pitch (floats), mod 32 = 4
#define ASP  68            // Red/As pitch over tokens
#define UP   516           // Us row pitch (floats)

// smem layout (float offsets); Us (phase B) reuses the XD region
#define XDSZ     (96 * XP)                 // one X+D buffer: 12672 floats
#define RED_OFF  (2 * XDSZ)                // 25344
#define AS_OFF   (RED_OFF + 8 * 32 * ASP)  // 42752
#define SM_FLOATS (AS_OFF + 32 * ASP)      // 44928 floats = 179712 B

// f32x2 packed-math helpers
#define FMA2(d, a, b) asm("fma.rn.f32x2 %0, %1, %2, %0;" : "+l"(d) : "l"(a), "l"(b))
#define PACK2(d, f)   asm("mov.b64 %0, {%1, %1};" : "=l"(d) : "f"(f))
#define UNPACK2(lo, hi, d) asm("mov.b64 {%0, %1}, %2;" : "=f"(lo), "=f"(hi) : "l"(d))

__device__ __forceinline__ unsigned su32(const void* p) {
    return (unsigned)__cvta_generic_to_shared(p);
}
#define CP16(dst, src) asm volatile("cp.async.cg.shared.global [%0], [%1], 16;" :: "r"(dst), "l"(src))
#define CP_COMMIT()    asm volatile("cp.async.commit_group;" ::: "memory")
#define CP_WAIT1()     asm volatile("cp.async.wait_group 1;" ::: "memory")
#define CP_WAIT0()     asm volatile("cp.async.wait_group 0;" ::: "memory")

// ---------------- device scratch ----------------
__device__ int    g_count[NB];
__device__ int    g_tok[NB][NTOK];
__device__ float2 g_gate[NB][NTOK];

// ---------------- K1: router (8 tokens per warp, f32x2) ----------------
__global__ __launch_bounds__(256)
void router_kernel(const float* __restrict__ x,
                   const float* __restrict__ rw) {
    extern __shared__ float Rs[];   // [E][H] = 64 KB
    for (int idx = threadIdx.x; idx < (E * H) / 4; idx += blockDim.x)
        ((float4*)Rs)[idx] = ((const float4*)rw)[idx];
    __syncthreads();

    const int w = threadIdx.x >> 5;
    const int l = threadIdx.x & 31;
    const int t0 = blockIdx.x * 64 + w * 8;

    const ulonglong2* xr = (const ulonglong2*)(x + (size_t)t0 * H);

    unsigned long long acc[E][8];
#pragma unroll
    for (int e = 0; e < E; e++)
#pragma unroll
        for (int j = 0; j < 8; j++) acc[e][j] = 0ull;

    for (int s = 0; s < 16; s++) {
        ulonglong2 xv[8];
#pragma unroll
        for (int j = 0; j < 8; j++)
            xv[j] = xr[j * (H / 4) + l + 32 * s];
#pragma unroll
        for (int e = 0; e < E; e++) {
            ulonglong2 wv = ((const ulonglong2*)(Rs + e * H))[l + 32 * s];
#pragma unroll
            for (int j = 0; j < 8; j++) {
                FMA2(acc[e][j], xv[j].x, wv.x);
                FMA2(acc[e][j], xv[j].y, wv.y);
            }
        }
    }

    float lg[E];
#pragma unroll
    for (int e = 0; e < E; e++) {
#pragma unroll
        for (int j = 0; j < 8; j++) {
            float s0, s1;
            UNPACK2(s0, s1, acc[e][j]);
            float v = s0 + s1;
#pragma unroll
            for (int o = 16; o > 0; o >>= 1) v += __shfl_xor_sync(0xffffffffu, v, o);
            if (l == j) lg[e] = v;
        }
    }

    if (l < 8) {
        int t = t0 + l;
        float m = lg[0];
#pragma unroll
        for (int e = 1; e < E; e++) m = fmaxf(m, lg[e]);
        float wgt[E]; float ssum = 0.f;
#pragma unroll
        for (int e = 0; e < E; e++) { wgt[e] = __expf(lg[e] - m); ssum += wgt[e]; }
        float inv = 1.f / ssum;

        int i1 = 0; float v1 = wgt[0];
#pragma unroll
        for (int e = 1; e < E; e++) if (wgt[e] > v1) { v1 = wgt[e]; i1 = e; }
        int i2 = -1; float v2 = -1.f;
#pragma unroll
        for (int e = 0; e < E; e++)
            if (e != i1 && wgt[e] > v2) { v2 = wgt[e]; i2 = e; }

        float g1 = v1 * inv, g2 = v2 * inv;
        int lo, hi; float glo, ghi;
        if (i1 < i2) { lo = i1; hi = i2; glo = g1; ghi = g2; }
        else         { lo = i2; hi = i1; glo = g2; ghi = g1; }
        int p = lo * 8 + hi;
        int slot = atomicAdd(&g_count[p], 1);
        g_tok[p][slot]  = t;
        g_gate[p][slot] = make_float2(glo, ghi);
    }
}

// ---------------- K2: expert compute, flat tile queue ----------------
// Phase A: C[64 tok][32 i] = X·D^T, split-K x8 (warp = k range), thread tile
//   8 tok x 8 i, cp.async double-buffered staging.
// Phase B: out[64][2048] = A·U via smem-staged Us[32 i][512 h], warp = 8
//   tokens, thread tile 8 tok x 16 h.
__global__ __launch_bounds__(256, 1)
void expert_kernel(const float* __restrict__ x,
                   const float* __restrict__ dw,
                   const float* __restrict__ uw,
                   float* __restrict__ out) {
    extern __shared__ float sm[];
    float* Red = sm + RED_OFF;
    float* As  = sm + AS_OFF;
    float* Us  = sm;                 // reuses XD region in phase B

    __shared__ int    pref[NB + 1];
    __shared__ int    Ts[TB];
    __shared__ float2 Gs[TB];

    const int tid = threadIdx.x;
    const int w = tid >> 5;          // warp = k-split group (A) / token group (B)
    const int l = tid & 31;
    const int tg = l & 7;            // phase A token interleave
    const int ig = l >> 3;           // phase A i interleave 0..3
    const int hg = l;                // phase B h lane

    // build flat tile prefix over buckets
    if (tid < NB) {
        int lo_ = tid >> 3, hi_ = tid & 7;
        pref[tid + 1] = (lo_ < hi_) ? (g_count[tid] + TB - 1) / TB : 0;
    }
    __syncthreads();
    if (tid == 0) {
        int s = 0;
        pref[0] = 0;
        for (int i = 1; i <= NB; i++) { s += pref[i]; pref[i] = s; }
    }
    __syncthreads();
    const int ntiles = pref[NB];

    for (int ft = blockIdx.x; ft < ntiles; ft += gridDim.x) {
        // largest p with pref[p] <= ft
        int a = 0, b = NB;
        while (b - a > 1) { int mM = (a + b) >> 1; if (pref[mM] <= ft) a = mM; else b = mM; }
        const int p  = a;
        const int lo = p >> 3, hi = p & 7;
        const int cnt  = g_count[p];
        const int base = (ft - pref[p]) * TB;
        const int n    = min(TB, cnt - base);

        __syncthreads();
        if (tid < TB) {
            int src = base + ((tid < n) ? tid : 0);
            Ts[tid] = g_tok[p][src];
            float2 gg = g_gate[p][src];
            if (tid >= n) gg = make_float2(0.f, 0.f);
            Gs[tid] = gg;
        }
        __syncthreads();

        // ================= Phase A =================
        unsigned long long accP[8][8];
#pragma unroll
        for (int u = 0; u < 8; u++)
#pragma unroll
            for (int v = 0; v < 8; v++) accP[u][v] = 0ull;

        auto stage = [&](int c, int bb) {
            float* dst = sm + bb * XDSZ;
            int koff = c * KC;
#pragma unroll
            for (int j = 0; j < 8; j++) {
                int idx = tid + 256 * j, r = idx >> 5, q = idx & 31;
                CP16(su32(dst + r * XP + 4 * q),
                     x + (size_t)Ts[r] * H + koff + 4 * q);
            }
#pragma unroll
            for (int j = 0; j < 4; j++) {
                int idx = tid + 256 * j, r = idx >> 5, q = idx & 31;
                int e = (r < 16) ? lo : hi;
                CP16(su32(dst + (64 + r) * XP + 4 * q),
                     dw + (size_t)(e * I16 + (r & 15)) * H + koff + 4 * q);
            }
        };

        stage(0, 0); CP_COMMIT();
        stage(1, 1); CP_COMMIT();

        for (int c = 0; c < NCH; c++) {
            if (c == NCH - 1) { CP_WAIT0(); } else { CP_WAIT1(); }
            __syncthreads();
            const ulonglong2* B4 = (const ulonglong2*)(sm + (c & 1) * XDSZ);

#pragma unroll
            for (int q2 = 0; q2 < 4; q2++) {
                const int kq = (w << 2) + q2;
                ulonglong2 xv[8];
#pragma unroll
                for (int u = 0; u < 8; u++)
                    xv[u] = B4[(tg + 8 * u) * 33 + kq];
#pragma unroll
                for (int v = 0; v < 8; v++) {
                    ulonglong2 dv = B4[(64 + ig + 4 * v) * 33 + kq];
#pragma unroll
                    for (int u = 0; u < 8; u++) {
                        FMA2(accP[u][v], xv[u].x, dv.x);
                        FMA2(accP[u][v], xv[u].y, dv.y);
                    }
                }
            }
            __syncthreads();
            if (c + 2 < NCH) { stage(c + 2, c & 1); CP_COMMIT(); }
        }

        // split-K partials -> Red[w][i][t]
#pragma unroll
        for (int u = 0; u < 8; u++)
#pragma unroll
            for (int v = 0; v < 8; v++) {
                float s0, s1;
                UNPACK2(s0, s1, accP[u][v]);
                Red[w * (32 * ASP) + (ig + 4 * v) * ASP + (tg + 8 * u)] = s0 + s1;
            }
        __syncthreads();

        // reduce + silu + gate -> As[i][t]
#pragma unroll
        for (int j = 0; j < 8; j++) {
            int idx = j * 256 + tid;
            int i = idx >> 6, t = idx & 63;
            float hv = 0.f;
#pragma unroll
            for (int kk = 0; kk < 8; kk++)
                hv += Red[kk * (32 * ASP) + i * ASP + t];
            float2 gg = Gs[t];
            float gate = (i < 16) ? gg.x : gg.y;
            float sig = 1.f / (1.f + __expf(-hv));
            As[i * ASP + t] = gate * hv * sig;
        }
        __syncthreads();             // As ready; XD region free

        // ================= Phase B =================
        for (int hb = 0; hb < 4; hb++) {
            // stage Us[32 i][512 h]: warp-uniform i-row per STS -> conflict-free
            float4 ub[16];
#pragma unroll
            for (int j = 0; j < 16; j++) {
                int idx = j * 256 + tid;
                int eiq = idx >> 9, h = idx & 511;
                int e2 = eiq >> 2, iq = eiq & 3;
                int eg = e2 ? hi : lo;
                ub[j] = *(const float4*)(uw + ((size_t)eg * H + hb * 512 + h) * I16 + 4 * iq);
            }
#pragma unroll
            for (int j = 0; j < 16; j++) {
                int idx = j * 256 + tid;
                int eiq = idx >> 9, h = idx & 511;
                int e2 = eiq >> 2, iq = eiq & 3;
                int rb = e2 * 16 + 4 * iq;
                Us[(rb + 0) * UP + h] = ub[j].x;
                Us[(rb + 1) * UP + h] = ub[j].y;
                Us[(rb + 2) * UP + h] = ub[j].z;
                Us[(rb + 3) * UP + h] = ub[j].w;
            }
            __syncthreads();

            unsigned long long acc[8][8];   // [token j][h-pair]
#pragma unroll
            for (int j = 0; j < 8; j++)
#pragma unroll
                for (int m = 0; m < 8; m++) acc[j][m] = 0ull;

#pragma unroll 4
            for (int k = 0; k < 32; k++) {
                float4 aA = *(const float4*)(As + k * ASP + w * 8);
                float4 aB = *(const float4*)(As + k * ASP + w * 8 + 4);
                unsigned long long ap[8];
                PACK2(ap[0], aA.x); PACK2(ap[1], aA.y);
                PACK2(ap[2], aA.z); PACK2(ap[3], aA.w);
                PACK2(ap[4], aB.x); PACK2(ap[5], aB.y);
                PACK2(ap[6], aB.z); PACK2(ap[7], aB.w);
#pragma unroll
                for (int m = 0; m < 4; m++) {
                    ulonglong2 uv = *(const ulonglong2*)(Us + k * UP + 4 * hg + 128 * m);
#pragma unroll
                    for (int j = 0; j < 8; j++) {
                        FMA2(acc[j][2 * m],     ap[j], uv.x);
                        FMA2(acc[j][2 * m + 1], ap[j], uv.y);
                    }
                }
            }

#pragma unroll
            for (int j = 0; j < 8; j++) {
                int tl = w * 8 + j;
                if (tl < n) {
                    float* orow = out + (size_t)Ts[tl] * H + hb * 512;
#pragma unroll
                    for (int m = 0; m < 4; m++) {
                        float4 ov;
                        UNPACK2(ov.x, ov.y, acc[j][2 * m]);
                        UNPACK2(ov.z, ov.w, acc[j][2 * m + 1]);
                        *(float4*)(orow + 4 * hg + 128 * m) = ov;
                    }
                }
            }
            __syncthreads();       // before next chunk overwrites Us
        }
    }
}

// ---------------- launch ----------------
extern "C" void kernel_launch(void* const* d_in, const int* in_sizes, int n_in,
                              void* d_out, int out_size) {
    const float* x  = (const float*)d_in[0];
    const float* rw = (const float*)d_in[1];
    const float* dw = (const float*)d_in[2];
    const float* uw = (const float*)d_in[3];
    float* out = (float*)d_out;

    const int rs_smem = E * H * sizeof(float);     // 64 KB
    const int ek_smem = SM_FLOATS * sizeof(float); // 179712 B
    cudaFuncSetAttribute(router_kernel, cudaFuncAttributeMaxDynamicSharedMemorySize, rs_smem);
    cudaFuncSetAttribute(expert_kernel, cudaFuncAttributeMaxDynamicSharedMemorySize, ek_smem);

    void* cnt_ptr = nullptr;
    cudaGetSymbolAddress(&cnt_ptr, g_count);
    cudaMemsetAsync(cnt_ptr, 0, NB * sizeof(int));

    router_kernel<<<NTOK / 64, 256, rs_smem>>>(x, rw);
    expert_kernel<<<148, 256, ek_smem>>>(x, dw, uw, out);
}